// round 7
// baseline (speedup 1.0000x reference)
#include <cuda_runtime.h>
#include <math.h>

#define BATCH 8
#define H 1024
#define W 1024
#define NPIX (H*W)
#define TOPK 4096
#define CAP  262144
#define RS   84           // 64 tile + 2*10 halo
#define RS2  (RS*RS)
#define NT   512
#define NBIN 65536
#define CCAP 6144
#define SORTN 8192
#define ULIM 0x30000000u
#define LISTCAP 512
#define MAXBIN 64

typedef unsigned long long ull;
typedef unsigned int uint;

// ---------------- scratch ----------------
__device__ ull      g_ckey[(size_t)BATCH*CAP];
__device__ int      g_ccnt[BATCH];
__device__ unsigned g_hist[BATCH*NBIN];
__device__ unsigned g_off[BATCH*NBIN];
__device__ ull      g_comp[(size_t)BATCH*SORTN];
__device__ unsigned g_ulo[BATCH];
__device__ int      g_flag[BATCH];

__global__ void reset_hist_kernel() {
    int i = blockIdx.x*1024 + threadIdx.x;
    uint4* h4 = (uint4*)g_hist;
    if (i < BATCH*NBIN/4) h4[i] = make_uint4(0,0,0,0);
}
__global__ void reset_cnt_kernel() {
    if (threadIdx.x < BATCH) g_ccnt[threadIdx.x] = 0;
}
__global__ void noop_kernel() {}

// ---------------- fused NMS ----------------
template<int LO>
__device__ __forceinline__ void hmax_f4(const float* __restrict__ src,
                                        float* __restrict__ dst, int tid) {
    static_assert((LO & 3) == 2, "alignment");
    constexpr int Wd = RS - 2*LO;
    constexpr int NC = Wd/4;
    constexpr int YN = Wd + 4;
    for (int c = tid; c < YN*NC; c += NT) {
        int ry = (LO-2) + c / NC;
        int cx = LO + (c % NC)*4;
        const float* p = src + ry*RS + (cx-2);
        float4 A = *(const float4*)p;
        float4 B = *(const float4*)(p+4);
        float m12 = fmaxf(A.y, A.z);
        float m34 = fmaxf(A.w, B.x);
        float m56 = fmaxf(B.y, B.z);
        float* q = dst + ry*RS + cx;
        *(float2*)q     = make_float2(fmaxf(fmaxf(A.x, m12), m34),
                                      fmaxf(fmaxf(m12, m34), B.y));
        *(float2*)(q+2) = make_float2(fmaxf(fmaxf(A.z, m34), m56),
                                      fmaxf(fmaxf(m34, m56), B.w));
    }
}

template<int LO>
__device__ __forceinline__ void hmax_fm4(const float* __restrict__ sS,
                                         const unsigned char* __restrict__ sU,
                                         float* __restrict__ dst, int tid) {
    static_assert((LO & 3) == 2, "alignment");
    constexpr int Wd = RS - 2*LO;
    constexpr int NC = Wd/4;
    constexpr int YN = Wd + 4;
    for (int c = tid; c < YN*NC; c += NT) {
        int ry = (LO-2) + c / NC;
        int cx = LO + (c % NC)*4;
        int base = ry*RS + (cx-2);
        float4 A = *(const float4*)(sS + base);
        float4 B = *(const float4*)(sS + base + 4);
        uint u0 = *(const uint*)(sU + base);
        uint u1 = *(const uint*)(sU + base + 4);
        float v0 = (u0 & 0x000000FFu) ? 0.f : A.x;
        float v1 = (u0 & 0x0000FF00u) ? 0.f : A.y;
        float v2 = (u0 & 0x00FF0000u) ? 0.f : A.z;
        float v3 = (u0 & 0xFF000000u) ? 0.f : A.w;
        float v4 = (u1 & 0x000000FFu) ? 0.f : B.x;
        float v5 = (u1 & 0x0000FF00u) ? 0.f : B.y;
        float v6 = (u1 & 0x00FF0000u) ? 0.f : B.z;
        float v7 = (u1 & 0xFF000000u) ? 0.f : B.w;
        float m12 = fmaxf(v1, v2);
        float m34 = fmaxf(v3, v4);
        float m56 = fmaxf(v5, v6);
        float* q = dst + ry*RS + cx;
        *(float2*)q     = make_float2(fmaxf(fmaxf(v0, m12), m34),
                                      fmaxf(fmaxf(m12, m34), v5));
        *(float2*)(q+2) = make_float2(fmaxf(fmaxf(v2, m34), m56),
                                      fmaxf(fmaxf(m34, m56), v7));
    }
}

template<int LO>
__device__ __forceinline__ void hmax_b4(const unsigned char* __restrict__ src,
                                        unsigned char* __restrict__ dst, int tid) {
    static_assert((LO & 3) == 0, "alignment");
    constexpr int Wd = RS - 2*LO;
    constexpr int NC = Wd/4;
    constexpr int YN = Wd + 4;
    for (int c = tid; c < YN*NC; c += NT) {
        int ry = (LO-2) + c / NC;
        int cx = LO + (c % NC)*4;
        int base = ry*RS + cx;
        uint W0 = *(const uint*)(src + base - 4);
        uint W1 = *(const uint*)(src + base);
        uint W2 = *(const uint*)(src + base + 4);
        uint v1 = __byte_perm(W0, W1, 0x5432);
        uint v2 = __byte_perm(W0, W1, 0x6543);
        uint v4 = __byte_perm(W1, W2, 0x4321);
        uint v5 = __byte_perm(W1, W2, 0x5432);
        *(uint*)(dst + base) = v1 | v2 | W1 | v4 | v5;
    }
}

#define VTREE_F(t, o) do { \
    float m12 = fmaxf(t[1], t[2]); \
    float m34 = fmaxf(t[3], t[4]); \
    float m56 = fmaxf(t[5], t[6]); \
    o[0] = fmaxf(fmaxf(t[0], m12), m34); \
    o[1] = fmaxf(fmaxf(m12, m34), t[5]); \
    o[2] = fmaxf(fmaxf(t[2], m34), m56); \
    o[3] = fmaxf(fmaxf(m34, m56), t[7]); \
} while(0)

__global__ __launch_bounds__(NT, 3) void nms_fused(const float* __restrict__ S) {
    extern __shared__ float sh[];
    float* sS = sh;
    float* sT = sh + RS2;
    unsigned char* sTb = (unsigned char*)sT;
    unsigned char* sM = (unsigned char*)(sh + 2*RS2);
    unsigned char* sU = sM + RS2;
    ull* sList = (ull*)(sM + 2*RS2);
    __shared__ int s_cnt, s_base;

    int tid = threadIdx.x;
    int b = blockIdx.z;
    int tx0 = blockIdx.x*64 - 10, ty0 = blockIdx.y*64 - 10;
    const float* img = S + (size_t)b*NPIX;

    bool interior = (blockIdx.x >= 1) & (blockIdx.x <= 14) &
                    (blockIdx.y >= 1) & (blockIdx.y <= 14);
    if (interior) {
        const float* rowbase = img + (size_t)ty0*W + (tx0 - 2);
        for (int i = tid; i < 84*22; i += NT) {
            int ry = i / 22, k = i - ry*22;
            float4 v = __ldg((const float4*)(rowbase + (size_t)ry*W) + k);
            int rx0 = 4*k - 2;
            float* q = sS + ry*RS + rx0;
            if (k > 0)  *(float2*)q     = make_float2(v.x, v.y);
            if (k < 21) *(float2*)(q+2) = make_float2(v.z, v.w);
        }
    } else {
        for (int i = tid; i < RS2; i += NT) {
            int ry = i/RS, rx = i - ry*RS;
            int gx = tx0+rx, gy = ty0+ry;
            bool in = ((unsigned)gx < W) & ((unsigned)gy < H);
            sS[i] = in ? __ldg(img + gy*W + gx) : 0.f;
        }
    }
    if (tid == 0) s_cnt = 0;
    __syncthreads();

    // stage 1
    hmax_f4<2>(sS, sT, tid); __syncthreads();
    {
        constexpr int LO = 2, Wd = RS - 2*LO;
        for (int c = tid; c < Wd*(Wd/4); c += NT) {
            int rx = LO + c % Wd;
            int ry0 = LO + (c / Wd)*4;
            float t[8], o[4];
            #pragma unroll
            for (int r = 0; r < 8; r++) t[r] = sT[(ry0-2+r)*RS + rx];
            VTREE_F(t, o);
            bool inx = ((unsigned)(tx0+rx) < W);
            #pragma unroll
            for (int r = 0; r < 4; r++) {
                int idx = (ry0+r)*RS + rx;
                bool in = inx & ((unsigned)(ty0+ry0+r) < H);
                sM[idx] = (unsigned char)(in && (sS[idx] == o[r]));
            }
        }
    }
    __syncthreads();

    // stage 2
    hmax_b4<4>(sM, sTb, tid); __syncthreads();
    {
        constexpr int LO = 4, Wd = RS - 2*LO;
        for (int c = tid; c < Wd*(Wd/4); c += NT) {
            int rx = LO + c % Wd;
            int ry0 = LO + (c / Wd)*4;
            unsigned t[8];
            #pragma unroll
            for (int r = 0; r < 8; r++) t[r] = sTb[(ry0-2+r)*RS + rx];
            unsigned m12 = t[1]|t[2], m34 = t[3]|t[4], m56 = t[5]|t[6];
            unsigned o[4] = { t[0]|m12|m34, m12|m34|t[5], t[2]|m34|m56, m34|m56|t[7] };
            #pragma unroll
            for (int r = 0; r < 4; r++)
                sU[(ry0+r)*RS + rx] = (unsigned char)(o[r] != 0u);
        }
    }
    __syncthreads();

    // stage 3
    hmax_fm4<6>(sS, sU, sT, tid); __syncthreads();
    {
        constexpr int LO = 6, Wd = RS - 2*LO;
        for (int c = tid; c < Wd*(Wd/4); c += NT) {
            int rx = LO + c % Wd;
            int ry0 = LO + (c / Wd)*4;
            float t[8], o[4];
            #pragma unroll
            for (int r = 0; r < 8; r++) t[r] = sT[(ry0-2+r)*RS + rx];
            VTREE_F(t, o);
            bool inx = ((unsigned)(tx0+rx) < W);
            #pragma unroll
            for (int r = 0; r < 4; r++) {
                int idx = (ry0+r)*RS + rx;
                bool in = inx & ((unsigned)(ty0+ry0+r) < H);
                bool u = sU[idx] != 0;
                float f = u ? 0.f : sS[idx];
                bool nw = (f == o[r]) && !u;
                sM[idx] = (unsigned char)(in && (sM[idx] || nw));
            }
        }
    }
    __syncthreads();

    // stage 4
    hmax_b4<8>(sM, sTb, tid); __syncthreads();
    {
        constexpr int LO = 8, Wd = RS - 2*LO;
        for (int c = tid; c < Wd*(Wd/4); c += NT) {
            int rx = LO + c % Wd;
            int ry0 = LO + (c / Wd)*4;
            unsigned t[8];
            #pragma unroll
            for (int r = 0; r < 8; r++) t[r] = sTb[(ry0-2+r)*RS + rx];
            unsigned m12 = t[1]|t[2], m34 = t[3]|t[4], m56 = t[5]|t[6];
            unsigned o[4] = { t[0]|m12|m34, m12|m34|t[5], t[2]|m34|m56, m34|m56|t[7] };
            #pragma unroll
            for (int r = 0; r < 4; r++)
                sU[(ry0+r)*RS + rx] = (unsigned char)(o[r] != 0u);
        }
    }
    __syncthreads();

    // stage 5
    hmax_fm4<10>(sS, sU, sT, tid); __syncthreads();
    {
        constexpr int LO = 10, Wd = RS - 2*LO;
        for (int c = tid; c < Wd*(Wd/4); c += NT) {
            int rx = LO + c % Wd;
            int ry0 = LO + (c / Wd)*4;
            float t[8], o[4];
            #pragma unroll
            for (int r = 0; r < 8; r++) t[r] = sT[(ry0-2+r)*RS + rx];
            VTREE_F(t, o);
            int gx = tx0 + rx;
            bool bx = (gx < 2) | (gx >= W-2);
            #pragma unroll
            for (int r = 0; r < 4; r++) {
                int idx = (ry0+r)*RS + rx;
                float s = sS[idx];
                bool u = sU[idx] != 0;
                float f = u ? 0.f : s;
                bool nw = (f == o[r]) && !u;
                bool m = sM[idx] || nw;
                int gy = ty0 + ry0 + r;
                bool border = bx | (gy < 2) | (gy >= H-2);
                if (m & !border & (s > 0.f)) {
                    unsigned ub = __float_as_uint(s);
                    unsigned bin = (ub >= ULIM) ? ((ub >> 12) & 0xFFFFu) : 0u;
                    atomicAdd(&g_hist[b*NBIN + bin], 1u);
                    ull key = ((ull)ub << 32) |
                              (ull)(0xFFFFFFFFu - (unsigned)(gy*W + gx));
                    int p = atomicAdd(&s_cnt, 1);
                    if (p < LISTCAP) sList[p] = key;
                    else {
                        int q = atomicAdd(&g_ccnt[b], 1);
                        if (q < CAP) g_ckey[(size_t)b*CAP + q] = key;
                    }
                }
            }
        }
        __syncthreads();
        if (tid == 0) {
            int c2 = s_cnt < LISTCAP ? s_cnt : LISTCAP;
            s_base = atomicAdd(&g_ccnt[b], c2);
            s_cnt = c2;
        }
        __syncthreads();
        int c2 = s_cnt, base = s_base;
        for (int i = tid; i < c2; i += NT) {
            int q = base + i;
            if (q < CAP) g_ckey[(size_t)b*CAP + q] = sList[i];
        }
    }
}

// ---------------- threshold + per-bin descending offsets ----------------
__global__ void __launch_bounds__(1024) threshold_kernel() {
    __shared__ unsigned part[1024];
    __shared__ int s_seg, s_flag, s_binlo;
    __shared__ unsigned s_ulo_sm;
    int b = blockIdx.x, tid = threadIdx.x;
    const unsigned* hist = g_hist + b*NBIN;

    unsigned s = 0;
    const uint4* h4 = (const uint4*)hist + tid*16;
    #pragma unroll
    for (int j = 0; j < 16; j++) {
        uint4 w = h4[j];
        s += w.x + w.y + w.z + w.w;
    }
    part[tid] = s;
    __syncthreads();
    for (int off = 1; off < 1024; off <<= 1) {
        unsigned v = part[tid] + ((tid+off < 1024) ? part[tid+off] : 0u);
        __syncthreads();
        part[tid] = v;
        __syncthreads();
    }
    unsigned total = part[0];
    unsigned need = total < (unsigned)TOPK ? total : (unsigned)TOPK;

    if (tid == 0) { s_seg = -1; s_flag = 0; s_binlo = NBIN; s_ulo_sm = 0; }
    __syncthreads();
    if (total > (unsigned)CCAP) {
        if (part[tid] >= need && (tid == 1023 || part[tid+1] < need)) s_seg = tid;
    }
    __syncthreads();

    if (tid == 0) {
        if (total > (unsigned)CCAP) {
            int seg = s_seg;
            unsigned running = (seg < 1023) ? part[seg+1] : 0u;
            int bin = -1; unsigned cnt = 0;
            for (int j = 63; j >= 0; j--) {
                running += hist[seg*64 + j];
                if (running >= need) { bin = seg*64 + j; cnt = running; break; }
            }
            if (bin <= 0 || cnt > (unsigned)CCAP) s_flag = 1;
            else {
                s_ulo_sm = (((unsigned)bin) << 12) | ULIM;
                s_binlo = bin;
            }
        } else {
            s_flag = 1;   // take-all / small-count: use exact fallback
        }
    }
    __syncthreads();

    // write descending suffix offsets; check max selected-bin population
    int binlo = s_binlo;
    unsigned run = (tid < 1023) ? part[tid+1] : 0u;
    bool over = false;
    #pragma unroll 4
    for (int j = 63; j >= 0; j--) {
        int bin = tid*64 + j;
        unsigned h = hist[bin];
        g_off[b*NBIN + bin] = run;
        run += h;
        if (bin >= binlo && h > (unsigned)MAXBIN) over = true;
    }
    if (over) s_flag = 1;
    __syncthreads();

    if (tid == 0) {
        g_ulo[b] = s_flag ? 0u : s_ulo_sm;
        g_flag[b] = s_flag;
    }
}

// ---------------- scatter: candidates >= u_lo to bin-sorted positions ----------------
__global__ void scatter_kernel() {
    int b = blockIdx.y;
    if (g_flag[b]) return;
    unsigned u_lo = g_ulo[b];
    int n = g_ccnt[b]; if (n > CAP) n = CAP;
    const ull* ck = g_ckey + (size_t)b*CAP;
    int stride = gridDim.x * blockDim.x;
    for (int i = blockIdx.x*blockDim.x + threadIdx.x; i < n; i += stride) {
        ull k = ck[i];
        unsigned u = (unsigned)(k >> 32);
        if (u >= u_lo) {
            unsigned bin = (u >> 12) & 0xFFFFu;
            unsigned pos = atomicAdd(&g_off[b*NBIN + bin], 1u);
            if (pos < SORTN) g_comp[(size_t)b*SORTN + pos] = k;
        }
    }
}

// ---------------- per-bin insertion sort (descending, exact) ----------------
__global__ void binsort_kernel() {
    int b = blockIdx.y;
    if (g_flag[b]) return;
    unsigned binlo = (g_ulo[b] >> 12) & 0xFFFFu;
    int bin = blockIdx.x*256 + threadIdx.x;
    if (bin < (int)binlo) return;
    int c = (int)g_hist[b*NBIN + bin];
    if (c < 2) return;
    int start = (int)g_off[b*NBIN + bin] - c;   // post-scatter value
    if (start >= TOPK) return;
    ull a[MAXBIN];
    ull* seg = g_comp + (size_t)b*SORTN + start;
    for (int i = 0; i < c; i++) a[i] = seg[i];
    for (int i = 1; i < c; i++) {
        ull key = a[i]; int j = i-1;
        while (j >= 0 && a[j] < key) { a[j+1] = a[j]; j--; }
        a[j+1] = key;
    }
    for (int i = 0; i < c; i++) seg[i] = a[i];
}

// ---------------- fallback: exact radix select + bitonic (per flagged batch) ----
__global__ void __launch_bounds__(1024) fallback_kernel() {
    extern __shared__ ull keys[];      // TOPK entries
    __shared__ unsigned fhist[2048];
    __shared__ ull s_hi;
    __shared__ int s_need, s_bin, s_cnt2;

    int b = blockIdx.x, tid = threadIdx.x;
    if (!g_flag[b]) return;

    int n = g_ccnt[b]; if (n > CAP) n = CAP;
    const ull* ck = g_ckey + (size_t)b*CAP;
    if (tid == 0) { s_hi = 0ull; s_need = TOPK; }
    __syncthreads();
    const int shifts[6] = {53, 42, 32, 21, 10, 0};
    const int nbits [6] = {11, 11, 10, 11, 11, 10};
    for (int lvl = 0; lvl < 6; lvl++) {
        int nb = nbits[lvl], sh = shifts[lvl], nbin = 1 << nb;
        for (int i = tid; i < nbin; i += 1024) fhist[i] = 0;
        __syncthreads();
        ull hi = s_hi;
        for (int i = tid; i < n; i += 1024) {
            ull c = ck[i];
            if ((c >> (sh + nb)) == hi)
                atomicAdd(&fhist[(unsigned)((c >> sh) & (ull)(nbin-1))], 1u);
        }
        __syncthreads();
        for (int off = 1; off < nbin; off <<= 1) {
            unsigned a0 = 0, a1 = 0;
            int i0 = tid, i1 = tid + 1024;
            if (i0 < nbin) a0 = fhist[i0] + ((i0+off < nbin) ? fhist[i0+off] : 0u);
            if (i1 < nbin) a1 = fhist[i1] + ((i1+off < nbin) ? fhist[i1+off] : 0u);
            __syncthreads();
            if (i0 < nbin) fhist[i0] = a0;
            if (i1 < nbin) fhist[i1] = a1;
            __syncthreads();
        }
        if (tid == 0) s_bin = -1;
        __syncthreads();
        int need = s_need;
        for (int i = tid; i < nbin; i += 1024) {
            unsigned Si = fhist[i];
            unsigned Sn = (i+1 < nbin) ? fhist[i+1] : 0u;
            if (Si >= (unsigned)need && Sn < (unsigned)need) s_bin = i;
        }
        __syncthreads();
        if (tid == 0) {
            int bin = s_bin;
            if (bin < 0) { bin = 0; s_need = (int)fhist[0]; }
            else {
                unsigned above = (bin+1 < nbin) ? fhist[bin+1] : 0u;
                s_need = s_need - (int)above;
            }
            s_hi = (s_hi << nb) | (ull)(unsigned)bin;
        }
        __syncthreads();
    }
    ull T = s_hi;
    if (tid == 0) s_cnt2 = 0;
    __syncthreads();
    for (int i = tid; i < n; i += 1024) {
        ull c = ck[i];
        if (c >= T) {
            int p = atomicAdd(&s_cnt2, 1);
            if (p < TOPK) keys[p] = c;
        }
    }
    __syncthreads();
    int cnt = s_cnt2; if (cnt > TOPK) cnt = TOPK;
    for (int i = tid; i < TOPK; i += 1024)
        if (i >= cnt) keys[i] = (ull)(0xFFFFFFFFu - (unsigned)i);
    __syncthreads();
    for (int k = 2; k <= TOPK; k <<= 1) {
        for (int j = k >> 1; j > 0; j >>= 1) {
            for (int t = tid; t < TOPK; t += 1024) {
                int p = t ^ j;
                if (p > t) {
                    ull a = keys[t], c2 = keys[p];
                    bool asc = ((t & k) == 0);
                    if ((a > c2) == asc) { keys[t] = c2; keys[p] = a; }
                }
            }
            __syncthreads();
        }
    }
    for (int i = tid; i < TOPK; i += 1024)
        g_comp[(size_t)b*SORTN + i] = keys[TOPK-1-i];
}

// ---------------- refinement (reads sorted keys from g_comp) ----------------
__device__ __forceinline__ float bil_tap(const float* img, float xf, float yf, float wgt) {
    bool valid = (xf >= 0.f) & (xf < (float)W) & (yf >= 0.f) & (yf < (float)H);
    int xc = (int)fminf(fmaxf(xf, 0.f), (float)(W-1));
    int yc = (int)fminf(fmaxf(yf, 0.f), (float)(H-1));
    float s = valid ? img[yc*W + xc] : 0.f;
    return s * wgt;
}

__global__ void refine_kernel(const float* __restrict__ S, float* __restrict__ out) {
    int g = blockIdx.x * blockDim.x + threadIdx.x;
    if (g >= BATCH*TOPK) return;
    int b = g / TOPK;
    int i = g - b*TOPK;
    ull key = g_comp[(size_t)b*SORTN + i];
    int idx = (int)(0xFFFFFFFFu - (unsigned)(key & 0xFFFFFFFFull));
    int ix = idx & (W-1), iy = idx >> 10;
    const float* img = S + (size_t)b*NPIX;

    float v[25];
    float mx = -1e30f;
    #pragma unroll
    for (int dy = 0; dy < 5; dy++) {
        int y = iy + dy - 2;
        #pragma unroll
        for (int dx = 0; dx < 5; dx++) {
            int x = ix + dx - 2;
            float val = (y >= 0 && y < H && x >= 0 && x < W) ? __ldg(img + y*W + x) : 0.f;
            v[dy*5 + dx] = val;
            mx = fmaxf(mx, val);
        }
    }
    float e[25];
    float S0 = 0.f, Sx = 0.f, Sy = 0.f;
    #pragma unroll
    for (int p = 0; p < 25; p++) {
        float ee = expf((v[p] - mx) * 10.0f);
        e[p] = ee;
        S0 += ee;
        Sx += ee * (float)(p % 5 - 2);
        Sy += ee * (float)(p / 5 - 2);
    }
    float rx = Sx / S0, ry = Sy / S0;
    float disp = 0.f;
    #pragma unroll
    for (int p = 0; p < 25; p++) {
        float ddx = ((float)(p % 5 - 2) - rx) * 0.5f;
        float ddy = ((float)(p / 5 - 2) - ry) * 0.5f;
        disp += e[p] * (ddx*ddx + ddy*ddy);
    }
    disp /= S0;

    float kx = ((float)ix + rx) / (float)(W-1) * 2.f - 1.f;
    float ky = ((float)iy + ry) / (float)(H-1) * 2.f - 1.f;

    float px = (kx + 1.f) * 0.5f * (float)(W-1);
    float py = (ky + 1.f) * 0.5f * (float)(H-1);
    float x0 = floorf(px), y0 = floorf(py);
    float wx1 = px - x0, wx0 = 1.f - wx1;
    float wy1 = py - y0, wy0 = 1.f - wy1;
    float score = bil_tap(img, x0,     y0,     wx0*wy0)
                + bil_tap(img, x0+1.f, y0,     wx1*wy0)
                + bil_tap(img, x0,     y0+1.f, wx0*wy1)
                + bil_tap(img, x0+1.f, y0+1.f, wx1*wy1);

    out[2*g + 0] = kx;
    out[2*g + 1] = ky;
    out[BATCH*TOPK*2 + g] = score;
    out[BATCH*TOPK*3 + g] = disp;
}

// ---------------- launch ----------------
extern "C" void kernel_launch(void* const* d_in, const int* in_sizes, int n_in,
                              void* d_out, int out_size) {
    const float* S = (const float*)d_in[0];
    float* out = (float*)d_out;

    const int nms_smem = 2*RS2*sizeof(float) + 2*RS2 + LISTCAP*sizeof(ull); // 74656
    const int fb_smem  = TOPK*sizeof(ull);                                   // 32768
    static int attr_set = 0;
    if (!attr_set) {
        cudaFuncSetAttribute(nms_fused, cudaFuncAttributeMaxDynamicSharedMemorySize, nms_smem);
        cudaFuncSetAttribute(fallback_kernel, cudaFuncAttributeMaxDynamicSharedMemorySize, fb_smem);
        attr_set = 1;
    }

    reset_hist_kernel<<<128, 1024>>>();       // 1
    reset_cnt_kernel<<<1, 32>>>();            // 2
    noop_kernel<<<1, 32>>>();                 // 3
    dim3 grid(16, 16, 8);
    nms_fused<<<grid, NT, nms_smem>>>(S);     // 4 <-- profiled slot
    threshold_kernel<<<BATCH, 1024>>>();      // 5
    scatter_kernel<<<dim3(64, BATCH), 256>>>();           // 6
    binsort_kernel<<<dim3(NBIN/256, BATCH), 256>>>();     // 7
    fallback_kernel<<<BATCH, 1024, fb_smem>>>();          // 8
    refine_kernel<<<(BATCH*TOPK + 127) / 128, 128>>>(S, out);  // 9
}

// round 8
// speedup vs baseline: 1.6336x; 1.6336x over previous
#include <cuda_runtime.h>
#include <math.h>

#define BATCH 8
#define H 1024
#define W 1024
#define NPIX (H*W)
#define TOPK 4096
#define CAP  262144
#define RS   84
#define RS2  (RS*RS)
#define NT   512
#define NBIN 65536
#define CCAP 6144
#define SORTN 8192
#define ULIM 0x30000000u
#define LISTCAP 512
#define MAXBIN2 2048
#define NSB 64

typedef unsigned long long ull;
typedef unsigned int uint;

// ---------------- scratch ----------------
__device__ ull      g_ckey[(size_t)BATCH*CAP];
__device__ int      g_ccnt[BATCH];
__device__ unsigned g_hist[BATCH*NBIN];
__device__ unsigned g_off[BATCH*NBIN];
__device__ ull      g_comp[(size_t)BATCH*SORTN];
__device__ unsigned g_ulo[BATCH];
__device__ int      g_flag[BATCH];

__global__ void reset_hist_kernel() {
    int i = blockIdx.x*1024 + threadIdx.x;
    uint4* h4 = (uint4*)g_hist;
    if (i < BATCH*NBIN/4) h4[i] = make_uint4(0,0,0,0);
}
__global__ void reset_cnt_kernel() {
    if (threadIdx.x < BATCH) g_ccnt[threadIdx.x] = 0;
}
__global__ void noop_kernel() {}

// ---------------- fused NMS ----------------
template<int LO>
__device__ __forceinline__ void hmax_f4(const float* __restrict__ src,
                                        float* __restrict__ dst, int tid) {
    static_assert((LO & 3) == 2, "alignment");
    constexpr int Wd = RS - 2*LO;
    constexpr int NC = Wd/4;
    constexpr int YN = Wd + 4;
    for (int c = tid; c < YN*NC; c += NT) {
        int ry = (LO-2) + c / NC;
        int cx = LO + (c % NC)*4;
        const float* p = src + ry*RS + (cx-2);
        float4 A = *(const float4*)p;
        float4 B = *(const float4*)(p+4);
        float m12 = fmaxf(A.y, A.z);
        float m34 = fmaxf(A.w, B.x);
        float m56 = fmaxf(B.y, B.z);
        float* q = dst + ry*RS + cx;
        *(float2*)q     = make_float2(fmaxf(fmaxf(A.x, m12), m34),
                                      fmaxf(fmaxf(m12, m34), B.y));
        *(float2*)(q+2) = make_float2(fmaxf(fmaxf(A.z, m34), m56),
                                      fmaxf(fmaxf(m34, m56), B.w));
    }
}

template<int LO>
__device__ __forceinline__ void hmax_fm4(const float* __restrict__ sS,
                                         const unsigned char* __restrict__ sU,
                                         float* __restrict__ dst, int tid) {
    static_assert((LO & 3) == 2, "alignment");
    constexpr int Wd = RS - 2*LO;
    constexpr int NC = Wd/4;
    constexpr int YN = Wd + 4;
    for (int c = tid; c < YN*NC; c += NT) {
        int ry = (LO-2) + c / NC;
        int cx = LO + (c % NC)*4;
        int base = ry*RS + (cx-2);
        float4 A = *(const float4*)(sS + base);
        float4 B = *(const float4*)(sS + base + 4);
        uint u0 = *(const uint*)(sU + base);
        uint u1 = *(const uint*)(sU + base + 4);
        float v0 = (u0 & 0x000000FFu) ? 0.f : A.x;
        float v1 = (u0 & 0x0000FF00u) ? 0.f : A.y;
        float v2 = (u0 & 0x00FF0000u) ? 0.f : A.z;
        float v3 = (u0 & 0xFF000000u) ? 0.f : A.w;
        float v4 = (u1 & 0x000000FFu) ? 0.f : B.x;
        float v5 = (u1 & 0x0000FF00u) ? 0.f : B.y;
        float v6 = (u1 & 0x00FF0000u) ? 0.f : B.z;
        float v7 = (u1 & 0xFF000000u) ? 0.f : B.w;
        float m12 = fmaxf(v1, v2);
        float m34 = fmaxf(v3, v4);
        float m56 = fmaxf(v5, v6);
        float* q = dst + ry*RS + cx;
        *(float2*)q     = make_float2(fmaxf(fmaxf(v0, m12), m34),
                                      fmaxf(fmaxf(m12, m34), v5));
        *(float2*)(q+2) = make_float2(fmaxf(fmaxf(v2, m34), m56),
                                      fmaxf(fmaxf(m34, m56), v7));
    }
}

template<int LO>
__device__ __forceinline__ void hmax_b4(const unsigned char* __restrict__ src,
                                        unsigned char* __restrict__ dst, int tid) {
    static_assert((LO & 3) == 0, "alignment");
    constexpr int Wd = RS - 2*LO;
    constexpr int NC = Wd/4;
    constexpr int YN = Wd + 4;
    for (int c = tid; c < YN*NC; c += NT) {
        int ry = (LO-2) + c / NC;
        int cx = LO + (c % NC)*4;
        int base = ry*RS + cx;
        uint W0 = *(const uint*)(src + base - 4);
        uint W1 = *(const uint*)(src + base);
        uint W2 = *(const uint*)(src + base + 4);
        uint v1 = __byte_perm(W0, W1, 0x5432);
        uint v2 = __byte_perm(W0, W1, 0x6543);
        uint v4 = __byte_perm(W1, W2, 0x4321);
        uint v5 = __byte_perm(W1, W2, 0x5432);
        *(uint*)(dst + base) = v1 | v2 | W1 | v4 | v5;
    }
}

#define VTREE_F(t, o) do { \
    float m12 = fmaxf(t[1], t[2]); \
    float m34 = fmaxf(t[3], t[4]); \
    float m56 = fmaxf(t[5], t[6]); \
    o[0] = fmaxf(fmaxf(t[0], m12), m34); \
    o[1] = fmaxf(fmaxf(m12, m34), t[5]); \
    o[2] = fmaxf(fmaxf(t[2], m34), m56); \
    o[3] = fmaxf(fmaxf(m34, m56), t[7]); \
} while(0)

__global__ __launch_bounds__(NT, 3) void nms_fused(const float* __restrict__ S) {
    extern __shared__ float sh[];
    float* sS = sh;
    float* sT = sh + RS2;
    unsigned char* sTb = (unsigned char*)sT;
    unsigned char* sM = (unsigned char*)(sh + 2*RS2);
    unsigned char* sU = sM + RS2;
    ull* sList = (ull*)(sM + 2*RS2);
    __shared__ int s_cnt, s_base;

    int tid = threadIdx.x;
    int b = blockIdx.z;
    int tx0 = blockIdx.x*64 - 10, ty0 = blockIdx.y*64 - 10;
    const float* img = S + (size_t)b*NPIX;

    bool interior = (blockIdx.x >= 1) & (blockIdx.x <= 14) &
                    (blockIdx.y >= 1) & (blockIdx.y <= 14);
    if (interior) {
        const float* rowbase = img + (size_t)ty0*W + (tx0 - 2);
        for (int i = tid; i < 84*22; i += NT) {
            int ry = i / 22, k = i - ry*22;
            float4 v = __ldg((const float4*)(rowbase + (size_t)ry*W) + k);
            int rx0 = 4*k - 2;
            float* q = sS + ry*RS + rx0;
            if (k > 0)  *(float2*)q     = make_float2(v.x, v.y);
            if (k < 21) *(float2*)(q+2) = make_float2(v.z, v.w);
        }
    } else {
        for (int i = tid; i < RS2; i += NT) {
            int ry = i/RS, rx = i - ry*RS;
            int gx = tx0+rx, gy = ty0+ry;
            bool in = ((unsigned)gx < W) & ((unsigned)gy < H);
            sS[i] = in ? __ldg(img + gy*W + gx) : 0.f;
        }
    }
    if (tid == 0) s_cnt = 0;
    __syncthreads();

    // stage 1
    hmax_f4<2>(sS, sT, tid); __syncthreads();
    {
        constexpr int LO = 2, Wd = RS - 2*LO;
        for (int c = tid; c < Wd*(Wd/4); c += NT) {
            int rx = LO + c % Wd;
            int ry0 = LO + (c / Wd)*4;
            float t[8], o[4];
            #pragma unroll
            for (int r = 0; r < 8; r++) t[r] = sT[(ry0-2+r)*RS + rx];
            VTREE_F(t, o);
            bool inx = ((unsigned)(tx0+rx) < W);
            #pragma unroll
            for (int r = 0; r < 4; r++) {
                int idx = (ry0+r)*RS + rx;
                bool in = inx & ((unsigned)(ty0+ry0+r) < H);
                sM[idx] = (unsigned char)(in && (sS[idx] == o[r]));
            }
        }
    }
    __syncthreads();

    // stage 2
    hmax_b4<4>(sM, sTb, tid); __syncthreads();
    {
        constexpr int LO = 4, Wd = RS - 2*LO;
        for (int c = tid; c < Wd*(Wd/4); c += NT) {
            int rx = LO + c % Wd;
            int ry0 = LO + (c / Wd)*4;
            unsigned t[8];
            #pragma unroll
            for (int r = 0; r < 8; r++) t[r] = sTb[(ry0-2+r)*RS + rx];
            unsigned m12 = t[1]|t[2], m34 = t[3]|t[4], m56 = t[5]|t[6];
            unsigned o[4] = { t[0]|m12|m34, m12|m34|t[5], t[2]|m34|m56, m34|m56|t[7] };
            #pragma unroll
            for (int r = 0; r < 4; r++)
                sU[(ry0+r)*RS + rx] = (unsigned char)(o[r] != 0u);
        }
    }
    __syncthreads();

    // stage 3
    hmax_fm4<6>(sS, sU, sT, tid); __syncthreads();
    {
        constexpr int LO = 6, Wd = RS - 2*LO;
        for (int c = tid; c < Wd*(Wd/4); c += NT) {
            int rx = LO + c % Wd;
            int ry0 = LO + (c / Wd)*4;
            float t[8], o[4];
            #pragma unroll
            for (int r = 0; r < 8; r++) t[r] = sT[(ry0-2+r)*RS + rx];
            VTREE_F(t, o);
            bool inx = ((unsigned)(tx0+rx) < W);
            #pragma unroll
            for (int r = 0; r < 4; r++) {
                int idx = (ry0+r)*RS + rx;
                bool in = inx & ((unsigned)(ty0+ry0+r) < H);
                bool u = sU[idx] != 0;
                float f = u ? 0.f : sS[idx];
                bool nw = (f == o[r]) && !u;
                sM[idx] = (unsigned char)(in && (sM[idx] || nw));
            }
        }
    }
    __syncthreads();

    // stage 4
    hmax_b4<8>(sM, sTb, tid); __syncthreads();
    {
        constexpr int LO = 8, Wd = RS - 2*LO;
        for (int c = tid; c < Wd*(Wd/4); c += NT) {
            int rx = LO + c % Wd;
            int ry0 = LO + (c / Wd)*4;
            unsigned t[8];
            #pragma unroll
            for (int r = 0; r < 8; r++) t[r] = sTb[(ry0-2+r)*RS + rx];
            unsigned m12 = t[1]|t[2], m34 = t[3]|t[4], m56 = t[5]|t[6];
            unsigned o[4] = { t[0]|m12|m34, m12|m34|t[5], t[2]|m34|m56, m34|m56|t[7] };
            #pragma unroll
            for (int r = 0; r < 4; r++)
                sU[(ry0+r)*RS + rx] = (unsigned char)(o[r] != 0u);
        }
    }
    __syncthreads();

    // stage 5
    hmax_fm4<10>(sS, sU, sT, tid); __syncthreads();
    {
        constexpr int LO = 10, Wd = RS - 2*LO;
        for (int c = tid; c < Wd*(Wd/4); c += NT) {
            int rx = LO + c % Wd;
            int ry0 = LO + (c / Wd)*4;
            float t[8], o[4];
            #pragma unroll
            for (int r = 0; r < 8; r++) t[r] = sT[(ry0-2+r)*RS + rx];
            VTREE_F(t, o);
            int gx = tx0 + rx;
            bool bx = (gx < 2) | (gx >= W-2);
            #pragma unroll
            for (int r = 0; r < 4; r++) {
                int idx = (ry0+r)*RS + rx;
                float s = sS[idx];
                bool u = sU[idx] != 0;
                float f = u ? 0.f : s;
                bool nw = (f == o[r]) && !u;
                bool m = sM[idx] || nw;
                int gy = ty0 + ry0 + r;
                bool border = bx | (gy < 2) | (gy >= H-2);
                if (m & !border & (s > 0.f)) {
                    unsigned ub = __float_as_uint(s);
                    unsigned bin = (ub >= ULIM) ? ((ub >> 12) & 0xFFFFu) : 0u;
                    atomicAdd(&g_hist[b*NBIN + bin], 1u);
                    ull key = ((ull)ub << 32) |
                              (ull)(0xFFFFFFFFu - (unsigned)(gy*W + gx));
                    int p = atomicAdd(&s_cnt, 1);
                    if (p < LISTCAP) sList[p] = key;
                    else {
                        int q = atomicAdd(&g_ccnt[b], 1);
                        if (q < CAP) g_ckey[(size_t)b*CAP + q] = key;
                    }
                }
            }
        }
        __syncthreads();
        if (tid == 0) {
            int c2 = s_cnt < LISTCAP ? s_cnt : LISTCAP;
            s_base = atomicAdd(&g_ccnt[b], c2);
            s_cnt = c2;
        }
        __syncthreads();
        int c2 = s_cnt, base = s_base;
        for (int i = tid; i < c2; i += NT) {
            int q = base + i;
            if (q < CAP) g_ckey[(size_t)b*CAP + q] = sList[i];
        }
    }
}

// ---------------- threshold + per-bin descending offsets ----------------
__global__ void __launch_bounds__(1024) threshold_kernel() {
    __shared__ unsigned part[1024];
    __shared__ int s_seg, s_flag, s_binlo;
    __shared__ unsigned s_ulo_sm;
    int b = blockIdx.x, tid = threadIdx.x;
    const unsigned* hist = g_hist + b*NBIN;

    unsigned s = 0;
    const uint4* h4 = (const uint4*)hist + tid*16;
    #pragma unroll
    for (int j = 0; j < 16; j++) {
        uint4 w = h4[j];
        s += w.x + w.y + w.z + w.w;
    }
    part[tid] = s;
    __syncthreads();
    for (int off = 1; off < 1024; off <<= 1) {
        unsigned v = part[tid] + ((tid+off < 1024) ? part[tid+off] : 0u);
        __syncthreads();
        part[tid] = v;
        __syncthreads();
    }
    unsigned total = part[0];
    unsigned need = total < (unsigned)TOPK ? total : (unsigned)TOPK;

    if (tid == 0) { s_seg = -1; s_flag = 0; s_binlo = NBIN; s_ulo_sm = 0; }
    __syncthreads();
    if (total > (unsigned)CCAP) {
        if (part[tid] >= need && (tid == 1023 || part[tid+1] < need)) s_seg = tid;
    }
    __syncthreads();

    if (tid == 0) {
        if (total > (unsigned)CCAP) {
            int seg = s_seg;
            unsigned running = (seg < 1023) ? part[seg+1] : 0u;
            int bin = -1; unsigned cnt = 0;
            for (int j = 63; j >= 0; j--) {
                running += hist[seg*64 + j];
                if (running >= need) { bin = seg*64 + j; cnt = running; break; }
            }
            if (bin <= 0 || cnt > (unsigned)CCAP) s_flag = 1;
            else {
                s_ulo_sm = (((unsigned)bin) << 12) | ULIM;
                s_binlo = bin;
            }
        } else {
            s_flag = 1;
        }
    }
    __syncthreads();

    int binlo = s_binlo;
    unsigned run = (tid < 1023) ? part[tid+1] : 0u;
    bool over = false;
    #pragma unroll 4
    for (int j = 63; j >= 0; j--) {
        int bin = tid*64 + j;
        unsigned h = hist[bin];
        g_off[b*NBIN + bin] = run;
        run += h;
        if (bin >= binlo && h > (unsigned)MAXBIN2) over = true;
    }
    if (over) s_flag = 1;
    __syncthreads();

    if (tid == 0) {
        g_ulo[b] = s_flag ? 0u : s_ulo_sm;
        g_flag[b] = s_flag;
    }
}

// ---------------- scatter ----------------
__global__ void scatter_kernel() {
    int b = blockIdx.y;
    if (g_flag[b]) return;
    unsigned u_lo = g_ulo[b];
    int n = g_ccnt[b]; if (n > CAP) n = CAP;
    const ull* ck = g_ckey + (size_t)b*CAP;
    int stride = gridDim.x * blockDim.x;
    for (int i = blockIdx.x*blockDim.x + threadIdx.x; i < n; i += stride) {
        ull k = ck[i];
        unsigned u = (unsigned)(k >> 32);
        if (u >= u_lo) {
            unsigned bin = (u >> 12) & 0xFFFFu;
            unsigned pos = atomicAdd(&g_off[b*NBIN + bin], 1u);
            if (pos < SORTN) g_comp[(size_t)b*SORTN + pos] = k;
        }
    }
}

// ---------------- per-bin block bitonic sort (descending, exact) ----------------
__global__ void __launch_bounds__(256) binsort_kernel() {
    __shared__ ull sk[MAXBIN2];
    int b = blockIdx.y;
    if (g_flag[b]) return;
    int binlo = (int)((g_ulo[b] >> 12) & 0xFFFFu);
    int tid = threadIdx.x;
    for (int bin = binlo + blockIdx.x; bin < NBIN; bin += NSB) {
        int c = (int)g_hist[b*NBIN + bin];
        if (c < 2) continue;
        int start = (int)g_off[b*NBIN + bin] - c;   // post-scatter value
        if (start >= TOPK) continue;
        int P = 1; while (P < c) P <<= 1;
        ull* seg = g_comp + (size_t)b*SORTN + start;
        for (int i = tid; i < P; i += 256) sk[i] = (i < c) ? seg[i] : 0ULL;
        __syncthreads();
        for (int k = 2; k <= P; k <<= 1) {
            for (int j = k >> 1; j > 0; j >>= 1) {
                for (int t = tid; t < P; t += 256) {
                    int p = t ^ j;
                    if (p > t) {
                        ull a = sk[t], c2 = sk[p];
                        bool desc = ((t & k) == 0);
                        if ((a < c2) == desc) { sk[t] = c2; sk[p] = a; }
                    }
                }
                __syncthreads();
            }
        }
        for (int i = tid; i < c; i += 256) seg[i] = sk[i];
        __syncthreads();
    }
}

// ---------------- fallback: exact radix select + bitonic ----------------
__global__ void __launch_bounds__(1024) fallback_kernel() {
    extern __shared__ ull keys[];
    __shared__ unsigned fhist[2048];
    __shared__ ull s_hi;
    __shared__ int s_need, s_bin, s_cnt2;

    int b = blockIdx.x, tid = threadIdx.x;
    if (!g_flag[b]) return;

    int n = g_ccnt[b]; if (n > CAP) n = CAP;
    const ull* ck = g_ckey + (size_t)b*CAP;
    if (tid == 0) { s_hi = 0ull; s_need = TOPK; }
    __syncthreads();
    const int shifts[6] = {53, 42, 32, 21, 10, 0};
    const int nbits [6] = {11, 11, 10, 11, 11, 10};
    for (int lvl = 0; lvl < 6; lvl++) {
        int nb = nbits[lvl], sh = shifts[lvl], nbin = 1 << nb;
        for (int i = tid; i < nbin; i += 1024) fhist[i] = 0;
        __syncthreads();
        ull hi = s_hi;
        for (int i = tid; i < n; i += 1024) {
            ull c = ck[i];
            if ((c >> (sh + nb)) == hi)
                atomicAdd(&fhist[(unsigned)((c >> sh) & (ull)(nbin-1))], 1u);
        }
        __syncthreads();
        for (int off = 1; off < nbin; off <<= 1) {
            unsigned a0 = 0, a1 = 0;
            int i0 = tid, i1 = tid + 1024;
            if (i0 < nbin) a0 = fhist[i0] + ((i0+off < nbin) ? fhist[i0+off] : 0u);
            if (i1 < nbin) a1 = fhist[i1] + ((i1+off < nbin) ? fhist[i1+off] : 0u);
            __syncthreads();
            if (i0 < nbin) fhist[i0] = a0;
            if (i1 < nbin) fhist[i1] = a1;
            __syncthreads();
        }
        if (tid == 0) s_bin = -1;
        __syncthreads();
        int need = s_need;
        for (int i = tid; i < nbin; i += 1024) {
            unsigned Si = fhist[i];
            unsigned Sn = (i+1 < nbin) ? fhist[i+1] : 0u;
            if (Si >= (unsigned)need && Sn < (unsigned)need) s_bin = i;
        }
        __syncthreads();
        if (tid == 0) {
            int bin = s_bin;
            if (bin < 0) { bin = 0; s_need = (int)fhist[0]; }
            else {
                unsigned above = (bin+1 < nbin) ? fhist[bin+1] : 0u;
                s_need = s_need - (int)above;
            }
            s_hi = (s_hi << nb) | (ull)(unsigned)bin;
        }
        __syncthreads();
    }
    ull T = s_hi;
    if (tid == 0) s_cnt2 = 0;
    __syncthreads();
    for (int i = tid; i < n; i += 1024) {
        ull c = ck[i];
        if (c >= T) {
            int p = atomicAdd(&s_cnt2, 1);
            if (p < TOPK) keys[p] = c;
        }
    }
    __syncthreads();
    int cnt = s_cnt2; if (cnt > TOPK) cnt = TOPK;
    for (int i = tid; i < TOPK; i += 1024)
        if (i >= cnt) keys[i] = (ull)(0xFFFFFFFFu - (unsigned)i);
    __syncthreads();
    for (int k = 2; k <= TOPK; k <<= 1) {
        for (int j = k >> 1; j > 0; j >>= 1) {
            for (int t = tid; t < TOPK; t += 1024) {
                int p = t ^ j;
                if (p > t) {
                    ull a = keys[t], c2 = keys[p];
                    bool asc = ((t & k) == 0);
                    if ((a > c2) == asc) { keys[t] = c2; keys[p] = a; }
                }
            }
            __syncthreads();
        }
    }
    for (int i = tid; i < TOPK; i += 1024)
        g_comp[(size_t)b*SORTN + i] = keys[TOPK-1-i];
}

// ---------------- refinement ----------------
__device__ __forceinline__ float bil_tap(const float* img, float xf, float yf, float wgt) {
    bool valid = (xf >= 0.f) & (xf < (float)W) & (yf >= 0.f) & (yf < (float)H);
    int xc = (int)fminf(fmaxf(xf, 0.f), (float)(W-1));
    int yc = (int)fminf(fmaxf(yf, 0.f), (float)(H-1));
    float s = valid ? img[yc*W + xc] : 0.f;
    return s * wgt;
}

__global__ void refine_kernel(const float* __restrict__ S, float* __restrict__ out) {
    int g = blockIdx.x * blockDim.x + threadIdx.x;
    if (g >= BATCH*TOPK) return;
    int b = g / TOPK;
    int i = g - b*TOPK;
    ull key = g_comp[(size_t)b*SORTN + i];
    int idx = (int)(0xFFFFFFFFu - (unsigned)(key & 0xFFFFFFFFull));
    int ix = idx & (W-1), iy = idx >> 10;
    const float* img = S + (size_t)b*NPIX;

    float v[25];
    float mx = -1e30f;
    #pragma unroll
    for (int dy = 0; dy < 5; dy++) {
        int y = iy + dy - 2;
        #pragma unroll
        for (int dx = 0; dx < 5; dx++) {
            int x = ix + dx - 2;
            float val = (y >= 0 && y < H && x >= 0 && x < W) ? __ldg(img + y*W + x) : 0.f;
            v[dy*5 + dx] = val;
            mx = fmaxf(mx, val);
        }
    }
    float e[25];
    float S0 = 0.f, Sx = 0.f, Sy = 0.f;
    #pragma unroll
    for (int p = 0; p < 25; p++) {
        float ee = expf((v[p] - mx) * 10.0f);
        e[p] = ee;
        S0 += ee;
        Sx += ee * (float)(p % 5 - 2);
        Sy += ee * (float)(p / 5 - 2);
    }
    float rx = Sx / S0, ry = Sy / S0;
    float disp = 0.f;
    #pragma unroll
    for (int p = 0; p < 25; p++) {
        float ddx = ((float)(p % 5 - 2) - rx) * 0.5f;
        float ddy = ((float)(p / 5 - 2) - ry) * 0.5f;
        disp += e[p] * (ddx*ddx + ddy*ddy);
    }
    disp /= S0;

    float kx = ((float)ix + rx) / (float)(W-1) * 2.f - 1.f;
    float ky = ((float)iy + ry) / (float)(H-1) * 2.f - 1.f;

    float px = (kx + 1.f) * 0.5f * (float)(W-1);
    float py = (ky + 1.f) * 0.5f * (float)(H-1);
    float x0 = floorf(px), y0 = floorf(py);
    float wx1 = px - x0, wx0 = 1.f - wx1;
    float wy1 = py - y0, wy0 = 1.f - wy1;
    float score = bil_tap(img, x0,     y0,     wx0*wy0)
                + bil_tap(img, x0+1.f, y0,     wx1*wy0)
                + bil_tap(img, x0,     y0+1.f, wx0*wy1)
                + bil_tap(img, x0+1.f, y0+1.f, wx1*wy1);

    out[2*g + 0] = kx;
    out[2*g + 1] = ky;
    out[BATCH*TOPK*2 + g] = score;
    out[BATCH*TOPK*3 + g] = disp;
}

// ---------------- launch ----------------
extern "C" void kernel_launch(void* const* d_in, const int* in_sizes, int n_in,
                              void* d_out, int out_size) {
    const float* S = (const float*)d_in[0];
    float* out = (float*)d_out;

    const int nms_smem = 2*RS2*sizeof(float) + 2*RS2 + LISTCAP*sizeof(ull);
    const int fb_smem  = TOPK*sizeof(ull);
    static int attr_set = 0;
    if (!attr_set) {
        cudaFuncSetAttribute(nms_fused, cudaFuncAttributeMaxDynamicSharedMemorySize, nms_smem);
        cudaFuncSetAttribute(fallback_kernel, cudaFuncAttributeMaxDynamicSharedMemorySize, fb_smem);
        attr_set = 1;
    }

    reset_hist_kernel<<<128, 1024>>>();       // 1
    reset_cnt_kernel<<<1, 32>>>();            // 2
    noop_kernel<<<1, 32>>>();                 // 3
    dim3 grid(16, 16, 8);
    nms_fused<<<grid, NT, nms_smem>>>(S);     // 4 <-- profiled slot
    threshold_kernel<<<BATCH, 1024>>>();      // 5
    scatter_kernel<<<dim3(64, BATCH), 256>>>();        // 6
    binsort_kernel<<<dim3(NSB, BATCH), 256>>>();       // 7
    fallback_kernel<<<BATCH, 1024, fb_smem>>>();       // 8
    refine_kernel<<<(BATCH*TOPK + 127) / 128, 128>>>(S, out);  // 9
}